// round 2
// baseline (speedup 1.0000x reference)
#include <cuda_runtime.h>

// Problem dims (fixed by reference)
#define BROWS 8192
#define DIN   256
#define NH1   512
#define NH2   256
#define DOUT  64

#define THRESHOLD 0.9f
#define NSPLIT 8
#define SEG (BROWS / NSPLIT)   // 1024
#define JT 64

typedef unsigned long long u64;

// Scratch (no cudaMalloc allowed)
__device__ float g_h1[BROWS * NH1];
__device__ float g_h2[BROWS * NH2];
__device__ float g_out[BROWS * DOUT];
__device__ float g_normed[BROWS * DOUT];

// ---------------------------------------------------------------------------
// packed fp32x2 helpers (sm_103a FFMA2 path; 2x fp32 FMA throughput)
// ---------------------------------------------------------------------------
__device__ __forceinline__ u64 fma2(u64 a, u64 b, u64 c) {
    u64 d;
    asm("fma.rn.f32x2 %0, %1, %2, %3;" : "=l"(d) : "l"(a), "l"(b), "l"(c));
    return d;
}
__device__ __forceinline__ u64 add2(u64 a, u64 b) {
    u64 d;
    asm("add.rn.f32x2 %0, %1, %2;" : "=l"(d) : "l"(a), "l"(b));
    return d;
}
__device__ __forceinline__ float lo32(u64 v) { return __uint_as_float((unsigned)(v & 0xffffffffu)); }
__device__ __forceinline__ float hi32(u64 v) { return __uint_as_float((unsigned)(v >> 32)); }

// ---------------------------------------------------------------------------
// GEMM (NT) body: C[M,N] = tanh(A[M,K] @ W[N,K]^T + b), BM=BN=64, BK=16, 256 thr
// ---------------------------------------------------------------------------
template<int N, int K>
__device__ __forceinline__ void gemm_nt_tanh_body(const float* __restrict__ A,
                                                  const float* __restrict__ W,
                                                  const float* __restrict__ bias,
                                                  float* __restrict__ C) {
    __shared__ float As[16][68];
    __shared__ float Ws[16][68];
    const int tid = threadIdx.x;
    const int tx = tid & 15, ty = tid >> 4;
    const int bm = blockIdx.y * 64, bn = blockIdx.x * 64;
    const int lr = tid >> 2;          // 0..63 row of tile
    const int lc = (tid & 3) << 2;    // 0,4,8,12 (float4 col)

    const float* Ag = A + (size_t)(bm + lr) * K + lc;
    const float* Wg = W + (size_t)(bn + lr) * K + lc;

    float acc[4][4] = {};
    for (int k0 = 0; k0 < K; k0 += 16) {
        float4 av = *(const float4*)(Ag + k0);
        float4 wv = *(const float4*)(Wg + k0);
        As[lc + 0][lr] = av.x; As[lc + 1][lr] = av.y;
        As[lc + 2][lr] = av.z; As[lc + 3][lr] = av.w;
        Ws[lc + 0][lr] = wv.x; Ws[lc + 1][lr] = wv.y;
        Ws[lc + 2][lr] = wv.z; Ws[lc + 3][lr] = wv.w;
        __syncthreads();
        #pragma unroll
        for (int k = 0; k < 16; k++) {
            float4 a4 = *(const float4*)&As[k][ty << 2];
            float4 w4 = *(const float4*)&Ws[k][tx << 2];
            float a[4] = {a4.x, a4.y, a4.z, a4.w};
            float w[4] = {w4.x, w4.y, w4.z, w4.w};
            #pragma unroll
            for (int i2 = 0; i2 < 4; i2++)
                #pragma unroll
                for (int j2 = 0; j2 < 4; j2++)
                    acc[i2][j2] = fmaf(a[i2], w[j2], acc[i2][j2]);
        }
        __syncthreads();
    }
    #pragma unroll
    for (int i2 = 0; i2 < 4; i2++) {
        const int row = bm + (ty << 2) + i2;
        #pragma unroll
        for (int j2 = 0; j2 < 4; j2++) {
            const int col = bn + (tx << 2) + j2;
            C[(size_t)row * N + col] = tanhf(acc[i2][j2] + bias[col]);
        }
    }
}

// Thin wrappers — scratch arrays referenced directly (no cudaGetSymbolAddress)
__global__ void gemm_l1(const float* __restrict__ x,
                        const float* __restrict__ W1,
                        const float* __restrict__ b1) {
    gemm_nt_tanh_body<NH1, DIN>(x, W1, b1, g_h1);
}
__global__ void gemm_l2(const float* __restrict__ W2,
                        const float* __restrict__ b2) {
    gemm_nt_tanh_body<NH2, NH1>(g_h1, W2, b2, g_h2);
}

// ---------------------------------------------------------------------------
// Final linear (no tanh) + per-row L2 norm epilogue -> g_out, g_normed
// N = 64 (full width in one block tile), K = 256, A = g_h2
// ---------------------------------------------------------------------------
__global__ void gemm_out_norm(const float* __restrict__ W,
                              const float* __restrict__ bias) {
    __shared__ float As[16][68];
    __shared__ float Ws[16][68];
    __shared__ float Cs[64][65];
    const int tid = threadIdx.x;
    const int tx = tid & 15, ty = tid >> 4;
    const int bm = blockIdx.x * 64;
    const int lr = tid >> 2;
    const int lc = (tid & 3) << 2;

    const float* Ag = g_h2 + (size_t)(bm + lr) * 256 + lc;
    const float* Wg = W + (size_t)lr * 256 + lc;   // W3 is [64,256]

    float acc[4][4] = {};
    for (int k0 = 0; k0 < 256; k0 += 16) {
        float4 av = *(const float4*)(Ag + k0);
        float4 wv = *(const float4*)(Wg + k0);
        As[lc + 0][lr] = av.x; As[lc + 1][lr] = av.y;
        As[lc + 2][lr] = av.z; As[lc + 3][lr] = av.w;
        Ws[lc + 0][lr] = wv.x; Ws[lc + 1][lr] = wv.y;
        Ws[lc + 2][lr] = wv.z; Ws[lc + 3][lr] = wv.w;
        __syncthreads();
        #pragma unroll
        for (int k = 0; k < 16; k++) {
            float4 a4 = *(const float4*)&As[k][ty << 2];
            float4 w4 = *(const float4*)&Ws[k][tx << 2];
            float a[4] = {a4.x, a4.y, a4.z, a4.w};
            float w[4] = {w4.x, w4.y, w4.z, w4.w};
            #pragma unroll
            for (int i2 = 0; i2 < 4; i2++)
                #pragma unroll
                for (int j2 = 0; j2 < 4; j2++)
                    acc[i2][j2] = fmaf(a[i2], w[j2], acc[i2][j2]);
        }
        __syncthreads();
    }
    #pragma unroll
    for (int i2 = 0; i2 < 4; i2++)
        #pragma unroll
        for (int j2 = 0; j2 < 4; j2++)
            Cs[(ty << 2) + i2][(tx << 2) + j2] = acc[i2][j2] + bias[(tx << 2) + j2];
    __syncthreads();

    const int warp = tid >> 5, lane = tid & 31;
    #pragma unroll
    for (int r8 = 0; r8 < 8; r8++) {
        const int r = warp * 8 + r8;
        const float v0 = Cs[r][lane];
        const float v1 = Cs[r][lane + 32];
        float s = v0 * v0 + v1 * v1;
        #pragma unroll
        for (int off = 16; off; off >>= 1)
            s += __shfl_xor_sync(0xffffffffu, s, off);
        const float inv = 1.0f / (sqrtf(s) + 1e-12f);
        const size_t base = (size_t)(bm + r) * 64;
        g_out[base + lane]        = v0;
        g_out[base + lane + 32]   = v1;
        g_normed[base + lane]      = v0 * inv;
        g_normed[base + lane + 32] = v1 * inv;
    }
}

// ---------------------------------------------------------------------------
// Fidelity + thresholded gather:  y[i] += sum_{j != i, (n_i.n_j)^2 >= 0.9} out[j]
// 2 threads per i-row (each owns 32 of the 64 dims), j-range split NSPLIT ways,
// packed f32x2 FMAs for the dot, conditional packed adds for the gather.
// ---------------------------------------------------------------------------
__global__ void fid_gather(float* __restrict__ y) {
    __shared__ float sn[JT * 64];
    __shared__ float so[JT * 64];
    const int tid = threadIdx.x;
    const int i = blockIdx.x * 128 + (tid >> 1);
    const int half16 = (tid & 1) * 16;   // offset in u64 units (16 u64 = 32 floats)

    const u64* nip = (const u64*)(g_normed + (size_t)i * 64) + half16;
    u64 ni[16], acc[16];
    #pragma unroll
    for (int u = 0; u < 16; u++) { ni[u] = nip[u]; acc[u] = 0ull; }

    const int jbase0 = blockIdx.y * SEG;
    for (int t = 0; t < SEG; t += JT) {
        const int jb = jbase0 + t;
        {   // cooperative tile load: JT rows of normed + out (32 KB)
            const float4* gn = (const float4*)(g_normed + (size_t)jb * 64);
            const float4* go = (const float4*)(g_out + (size_t)jb * 64);
            float4* s4n = (float4*)sn;
            float4* s4o = (float4*)so;
            #pragma unroll
            for (int u = 0; u < 4; u++) {
                const int idx = tid + 256 * u;
                s4n[idx] = gn[idx];
                s4o[idx] = go[idx];
            }
        }
        __syncthreads();
        #pragma unroll 2
        for (int jj = 0; jj < JT; jj++) {
            const u64* nj = (const u64*)(sn + jj * 64) + half16;
            u64 p = 0ull;
            #pragma unroll
            for (int u = 0; u < 16; u++) p = fma2(ni[u], nj[u], p);
            const float part = lo32(p) + hi32(p);
            const float dot = part + __shfl_xor_sync(0xffffffffu, part, 1);
            const int j = jb + jj;
            if (dot * dot >= THRESHOLD && j != i) {
                const u64* oj = (const u64*)(so + jj * 64) + half16;
                #pragma unroll
                for (int u = 0; u < 16; u++) acc[u] = add2(acc[u], oj[u]);
            }
        }
        __syncthreads();
    }

    float* yp = y + (size_t)i * 64 + (tid & 1) * 32;
    #pragma unroll
    for (int u = 0; u < 16; u++) {
        atomicAdd(yp + 2 * u,     lo32(acc[u]));
        atomicAdd(yp + 2 * u + 1, hi32(acc[u]));
    }
}

__global__ void zero_out(float* __restrict__ y, int n) {
    const int t = blockIdx.x * 256 + threadIdx.x;
    if (t < n) y[t] = 0.0f;
}

// ---------------------------------------------------------------------------
extern "C" void kernel_launch(void* const* d_in, const int* in_sizes, int n_in,
                              void* d_out, int out_size) {
    const float* x  = (const float*)d_in[0];
    const float* W1 = (const float*)d_in[1];
    const float* b1 = (const float*)d_in[2];
    const float* W2 = (const float*)d_in[3];
    const float* b2 = (const float*)d_in[4];
    const float* W3 = (const float*)d_in[5];
    const float* b3 = (const float*)d_in[6];
    float* y = (float*)d_out;

    // Layer 1: [8192,256] -> [8192,512], tanh
    gemm_l1<<<dim3(NH1 / 64, BROWS / 64), 256>>>(x, W1, b1);
    // Layer 2: [8192,512] -> [8192,256], tanh
    gemm_l2<<<dim3(NH2 / 64, BROWS / 64), 256>>>(W2, b2);
    // Layer 3 + row norms -> g_out, g_normed
    gemm_out_norm<<<BROWS / 64, 256>>>(W3, b3);
    // Output accumulator
    zero_out<<<(BROWS * DOUT + 255) / 256, 256>>>(y, BROWS * DOUT);
    // Fidelity adjacency gather
    fid_gather<<<dim3(BROWS / 128, NSPLIT), 256>>>(y);
}